// round 2
// baseline (speedup 1.0000x reference)
#include <cuda_runtime.h>
#include <math.h>

#define Dn   512
#define FDn  2048
#define On   256
#define Kn   49
#define Bn   4
#define Cn   256
#define Hn   64
#define Wn   48
#define HWn  3072
#define Nn   32
#define KOn  (Kn*On)   // 12544

__device__ float g_eps [Nn*FDn];
__device__ float g_v   [Nn*Dn];
__device__ float g_bvec[Nn*KOn];
__device__ float g_A   [Hn*On];
__device__ float g_Bm  [Wn*On];
__device__ float g_eGA [Nn*Kn*Hn];
__device__ float g_eGB [Nn*Kn*Wn];
__device__ float g_eapp[Bn*Kn*HWn];
__device__ int   g_rank[Nn];

// embed element: dd<256 -> sin(z / 1000^((2dd+1)/512)); else cos(z / 1000^((2(dd-256))/512))
// double path: immune to fast-math sinf range reduction (args up to ~63).
__device__ __forceinline__ float embed_val(float z, int dd) {
    if (dd < 256) {
        double den = pow(1000.0, (2.0 * dd + 1.0) / 512.0);
        return (float)sin((double)z / den);
    } else {
        double den = pow(1000.0, (2.0 * (dd - 256)) / 512.0);
        return (float)cos((double)z / den);
    }
}

// ---------------- eps: (N, 4*D) positional embedding of roi coords ----------------
__global__ void k_eps(const float* __restrict__ rois) {
    int n = blockIdx.x;
    float c0 = rois[n*5+1], c1 = rois[n*5+2], c2 = rois[n*5+3], c3 = rois[n*5+4];
    for (int i = threadIdx.x; i < FDn; i += blockDim.x) {
        int c  = i >> 9;
        int dd = i & 511;
        float z = (c >= 2) ? ((c == 3) ? c3 : c2) : ((c == 1) ? c1 : c0);
        g_eps[n*FDn + i] = embed_val(z, dd);
    }
}

// ---------------- A[h,o], B[w,o]: separable img projection ----------------
// img[h,w,o] = A[h,o] + B[w,o];  A = ex @ W_im[:, :D]^T,  B = ey @ W_im[:, D:]^T
__global__ void k_AB(const float* __restrict__ W_im) {
    __shared__ float pe[Dn];
    int j = blockIdx.x;
    bool isA = (j < Hn);
    float z = (float)(isA ? j : (j - Hn));
    for (int dd = threadIdx.x; dd < Dn; dd += blockDim.x)
        pe[dd] = embed_val(z, dd);
    __syncthreads();
    int o = threadIdx.x;  // 256 threads
    const float4* w4 = (const float4*)(W_im + (size_t)o * (2*Dn) + (isA ? 0 : Dn));
    const float4* p4 = (const float4*)pe;
    float acc = 0.f;
    #pragma unroll 8
    for (int f = 0; f < Dn/4; ++f) {
        float4 wv = w4[f], pv = p4[f];
        acc += wv.x*pv.x + wv.y*pv.y + wv.z*pv.z + wv.w*pv.w;
    }
    if (isA) g_A[j*On + o] = acc;
    else     g_Bm[(j-Hn)*On + o] = acc;
}

// ---------------- v[n,d] = V_box[d,:] . eps[n,:]  (grid: 8 d-tiles x 8 n-groups) ----
__global__ void k_v(const float* __restrict__ V_box) {
    __shared__ float eps_s[4*FDn]; // 32 KB
    int dp = blockIdx.x, ng = blockIdx.y;
    for (int i = threadIdx.x; i < 4*FDn; i += 256)
        eps_s[i] = g_eps[ng*4*FDn + i];
    __syncthreads();
    int dl = threadIdx.x & 63;
    int nn = threadIdx.x >> 6;
    int d  = dp*64 + dl;
    int n  = ng*4 + nn;
    const float4* vb = (const float4*)(V_box + (size_t)d * FDn);
    const float4* ep = (const float4*)(eps_s + nn*FDn);
    float acc = 0.f;
    #pragma unroll 4
    for (int f = 0; f < FDn/4; ++f) {
        float4 a = vb[f], b = ep[f];
        acc += a.x*b.x + a.y*b.y + a.z*b.z + a.w*b.w;
    }
    g_v[n*Dn + d] = acc;
}

// ---------------- bvec[n,ko] = W_box[ko,:] . v[n,:]  (205M MAC) ----------------
__global__ void k_bvec(const float* __restrict__ W_box) {
    extern __shared__ float v_s[]; // 32*512 = 64 KB
    for (int i = threadIdx.x; i < Nn*Dn; i += 256) v_s[i] = g_v[i];
    __syncthreads();
    int kol = threadIdx.x & 63;
    int ng  = threadIdx.x >> 6;     // 0..3
    int n0  = ng * 8;
    int ko  = blockIdx.x * 64 + kol;
    const float4* wb = (const float4*)(W_box + (size_t)ko * Dn);
    float acc[8] = {0,0,0,0,0,0,0,0};
    #pragma unroll 2
    for (int f = 0; f < Dn/4; ++f) {
        float4 wv = wb[f];
        #pragma unroll
        for (int j = 0; j < 8; ++j) {
            float4 vv = *(const float4*)(v_s + (n0+j)*Dn + f*4); // broadcast LDS
            acc[j] += wv.x*vv.x + wv.y*vv.y + wv.z*vv.z + wv.w*vv.w;
        }
    }
    #pragma unroll
    for (int j = 0; j < 8; ++j)
        g_bvec[(size_t)(n0+j)*KOn + ko] = acc[j];
}

// ---------------- eGA[n,k,h] = exp( bvec[n,k,:] . A[h,:] ) ----------------
__global__ void k_GA() {
    extern __shared__ float A_s[]; // [o*65 + h], 256*65 floats
    int n = blockIdx.x;
    for (int i = threadIdx.x; i < Hn*On; i += 256) {
        int h = i >> 8, o = i & 255;
        A_s[o*65 + h] = g_A[i];
    }
    __syncthreads();
    for (int idx = threadIdx.x; idx < Kn*Hn; idx += 256) {
        int k = idx >> 6, h = idx & 63;
        const float4* bp = (const float4*)(g_bvec + ((size_t)n*Kn + k)*On);
        float acc = 0.f;
        #pragma unroll 4
        for (int o4 = 0; o4 < On/4; ++o4) {
            float4 bv = bp[o4];
            int ob = o4*4;
            acc += bv.x*A_s[ ob   *65 + h] + bv.y*A_s[(ob+1)*65 + h]
                 + bv.z*A_s[(ob+2)*65 + h] + bv.w*A_s[(ob+3)*65 + h];
        }
        g_eGA[n*Kn*Hn + idx] = expf(acc);
    }
}

// ---------------- eGB[n,k,w] = exp( bvec[n,k,:] . B[w,:] ) ----------------
__global__ void k_GB() {
    extern __shared__ float B_s[]; // [o*49 + w], 256*49 floats
    int n = blockIdx.x;
    for (int i = threadIdx.x; i < Wn*On; i += 256) {
        int w = i >> 8, o = i & 255;
        B_s[o*49 + w] = g_Bm[i];
    }
    __syncthreads();
    for (int idx = threadIdx.x; idx < Kn*Wn; idx += 256) {
        int k = idx / 48, w = idx - k*48;
        const float4* bp = (const float4*)(g_bvec + ((size_t)n*Kn + k)*On);
        float acc = 0.f;
        #pragma unroll 4
        for (int o4 = 0; o4 < On/4; ++o4) {
            float4 bv = bp[o4];
            int ob = o4*4;
            acc += bv.x*B_s[ ob   *49 + w] + bv.y*B_s[(ob+1)*49 + w]
                 + bv.z*B_s[(ob+2)*49 + w] + bv.w*B_s[(ob+3)*49 + w];
        }
        g_eGB[n*Kn*Wn + idx] = expf(acc);
    }
}

// ---------------- eapp[b,k,p] = exp( conv_b[k] + sum_c conv_w[k,c]*x[b,c,p] ) ----
// block: 128 threads = 4 k-groups x 32 lanes; each thread: 2 pixels x 13 k's
__global__ void k_eapp(const float* __restrict__ x,
                       const float* __restrict__ conv_w,
                       const float* __restrict__ conv_b) {
    extern __shared__ float sm[];
    float* cw_s = sm;            // 52*256 (padded to 52 k-rows, zeros beyond 49)
    float* x_s  = sm + 52*256;   // 64 c x 64 p
    int b   = blockIdx.y;
    int px0 = blockIdx.x * 64;
    for (int i = threadIdx.x; i < 52*256; i += 128)
        cw_s[i] = (i < Kn*Cn) ? conv_w[i] : 0.0f;
    int lane = threadIdx.x & 31;
    int ks   = threadIdx.x >> 5;
    int k0   = ks * 13;
    float acc0[13], acc1[13];
    #pragma unroll
    for (int kk = 0; kk < 13; ++kk) { acc0[kk] = 0.f; acc1[kk] = 0.f; }

    for (int c0 = 0; c0 < Cn; c0 += 64) {
        __syncthreads();
        for (int i = threadIdx.x; i < 64*64; i += 128) {
            int c = i >> 6, p = i & 63;
            x_s[i] = x[((size_t)b*Cn + c0 + c)*HWn + px0 + p];
        }
        __syncthreads();
        #pragma unroll 4
        for (int c = 0; c < 64; ++c) {
            float xv0 = x_s[c*64 + lane*2];
            float xv1 = x_s[c*64 + lane*2 + 1];
            #pragma unroll
            for (int kk = 0; kk < 13; ++kk) {
                float wv = cw_s[(k0+kk)*256 + c0 + c]; // uniform -> broadcast
                acc0[kk] += wv * xv0;
                acc1[kk] += wv * xv1;
            }
        }
    }
    int p0 = px0 + lane*2;
    #pragma unroll
    for (int kk = 0; kk < 13; ++kk) {
        int k = k0 + kk;
        if (k < Kn) {
            float bias = conv_b[k];
            g_eapp[((size_t)b*Kn + k)*HWn + p0    ] = expf(acc0[kk] + bias);
            g_eapp[((size_t)b*Kn + k)*HWn + p0 + 1] = expf(acc1[kk] + bias);
        }
    }
}

// ---------------- rank (inverse of stable argsort of idx) ----------------
__global__ void k_rank(const float* __restrict__ rois) {
    int n = threadIdx.x;
    int my = (int)rois[n*5];
    int r = 0;
    for (int j = 0; j < Nn; ++j) {
        int o = (int)rois[j*5];
        r += (o < my) || (o == my && j < n);
    }
    g_rank[n] = r;
}

// ---------------- final: softmax over k, permuted write (77 MB, store-bound) ----
__global__ void k_final(float* __restrict__ out) {
    __shared__ float eGA_s[Kn*Hn]; // 12.25 KB
    __shared__ float eGB_s[Kn*Wn]; //  9.2 KB
    int nb = blockIdx.y;
    int n = nb >> 2, b = nb & 3;
    for (int i = threadIdx.x; i < Kn*Hn; i += 256) eGA_s[i] = g_eGA[n*Kn*Hn + i];
    for (int i = threadIdx.x; i < Kn*Wn; i += 256) eGB_s[i] = g_eGB[n*Kn*Wn + i];
    __syncthreads();
    int p = blockIdx.x*256 + threadIdx.x;
    int h = p / 48;
    int w = p - h*48;
    const float* ea = g_eapp + (size_t)b*Kn*HWn + p;
    float s = 0.f;
    #pragma unroll
    for (int k = 0; k < Kn; ++k)
        s += eGA_s[k*Hn + h] * eGB_s[k*Wn + w] * ea[(size_t)k*HWn];
    float inv = 1.0f / s;
    int r = g_rank[n];
    float* op = out + ((size_t)(r*Bn + b)*Kn)*HWn + p;
    #pragma unroll
    for (int k = 0; k < Kn; ++k)
        op[(size_t)k*HWn] = eGA_s[k*Hn + h] * eGB_s[k*Wn + w] * ea[(size_t)k*HWn] * inv;
}

extern "C" void kernel_launch(void* const* d_in, const int* in_sizes, int n_in,
                              void* d_out, int out_size) {
    const float* x      = (const float*)d_in[0];
    const float* rois   = (const float*)d_in[1];
    const float* V_box  = (const float*)d_in[2];
    const float* W_box  = (const float*)d_in[3];
    const float* W_im   = (const float*)d_in[4];
    const float* conv_w = (const float*)d_in[5];
    const float* conv_b = (const float*)d_in[6];
    float* out = (float*)d_out;

    cudaFuncSetAttribute(k_bvec, cudaFuncAttributeMaxDynamicSharedMemorySize, 65536);
    cudaFuncSetAttribute(k_GA,   cudaFuncAttributeMaxDynamicSharedMemorySize, 256*65*4);
    cudaFuncSetAttribute(k_GB,   cudaFuncAttributeMaxDynamicSharedMemorySize, 256*49*4);
    cudaFuncSetAttribute(k_eapp, cudaFuncAttributeMaxDynamicSharedMemorySize, 52*256*4 + 64*64*4);

    k_eps <<<Nn, 256>>>(rois);
    k_AB  <<<Hn + Wn, 256>>>(W_im);
    k_rank<<<1, 32>>>(rois);
    k_v   <<<dim3(8, 8), 256>>>(V_box);
    k_bvec<<<KOn/64, 256, 65536>>>(W_box);
    k_GA  <<<Nn, 256, 256*65*4>>>();
    k_GB  <<<Nn, 256, 256*49*4>>>();
    k_eapp<<<dim3(HWn/64, Bn), 128, 52*256*4 + 64*64*4>>>(x, conv_w, conv_b);
    k_final<<<dim3(HWn/256, Nn*Bn), 256>>>(out);
}

// round 3
// speedup vs baseline: 1.4787x; 1.4787x over previous
#include <cuda_runtime.h>
#include <math.h>

#define Dn   512
#define FDn  2048
#define On   256
#define Kn   49
#define Bn   4
#define Cn   256
#define Hn   64
#define Wn   48
#define HWn  3072
#define Nn   32
#define KOn  (Kn*On)   // 12544
#define KSPLIT 16

typedef unsigned long long u64;

__device__ float  g_eps [Nn*FDn];
__device__ float  g_vp  [KSPLIT*Nn*Dn];
__device__ float  g_bvec[Nn*KOn];
__device__ float  g_A   [Hn*On];
__device__ float  g_Bm  [Wn*On];
__device__ float  g_eGA [Nn*Kn*Hn];
__device__ float  g_eGB [Nn*Kn*Wn];
__device__ float  g_eapp[Bn*Kn*HWn];
__device__ int    g_rank[Nn];
__device__ double g_invden[512];

// packed f32x2 FMA: acc.{lo,hi} += a.{lo,hi} * b.{lo,hi}
__device__ __forceinline__ void ffma2(u64 &acc, u64 a, u64 b) {
    asm volatile("fma.rn.f32x2 %0, %1, %2, %0;" : "+l"(acc) : "l"(a), "l"(b));
}
__device__ __forceinline__ float hsum2(u64 a) {
    float2 f = *reinterpret_cast<float2*>(&a);
    return f.x + f.y;
}

// ---------------- denominator table: 512 double pows, once ----------------
__global__ void k_tab() {
    int dd = threadIdx.x + blockIdx.x * blockDim.x;
    if (dd < 512) {
        double e = (dd < 256) ? (2.0 * dd + 1.0) / 512.0
                              : (2.0 * (dd - 256)) / 512.0;
        g_invden[dd] = pow(1000.0, -e);
    }
}

__device__ __forceinline__ float embed_val(float z, int dd) {
    double a = (double)z * g_invden[dd];
    return (float)((dd < 256) ? sin(a) : cos(a));
}

// ---------------- fused: eps (blocks 0..31) | A/B (32..143) | rank (144) ----
__global__ void k_pre(const float* __restrict__ rois,
                      const float* __restrict__ W_im) {
    int bid = blockIdx.x;
    if (bid < Nn) {
        int n = bid;
        float c0 = rois[n*5+1], c1 = rois[n*5+2], c2 = rois[n*5+3], c3 = rois[n*5+4];
        for (int i = threadIdx.x; i < FDn; i += blockDim.x) {
            int c  = i >> 9;
            int dd = i & 511;
            float z = (c >= 2) ? ((c == 3) ? c3 : c2) : ((c == 1) ? c1 : c0);
            g_eps[n*FDn + i] = embed_val(z, dd);
        }
    } else if (bid < Nn + Hn + Wn) {
        __shared__ float pe[Dn];
        int j = bid - Nn;
        bool isA = (j < Hn);
        float z = (float)(isA ? j : (j - Hn));
        for (int dd = threadIdx.x; dd < Dn; dd += blockDim.x)
            pe[dd] = embed_val(z, dd);
        __syncthreads();
        int o = threadIdx.x;  // 256 threads
        const ulonglong2* w2 = (const ulonglong2*)(W_im + (size_t)o * (2*Dn) + (isA ? 0 : Dn));
        const ulonglong2* p2 = (const ulonglong2*)pe;
        u64 acc = 0;
        #pragma unroll 8
        for (int f = 0; f < Dn/4; ++f) {
            ulonglong2 wv = w2[f], pv = p2[f];
            ffma2(acc, wv.x, pv.x);
            ffma2(acc, wv.y, pv.y);
        }
        if (isA) g_A[j*On + o] = hsum2(acc);
        else     g_Bm[(j-Hn)*On + o] = hsum2(acc);
    } else {
        int n = threadIdx.x;
        if (n < Nn) {
            int my = (int)rois[n*5];
            int r = 0;
            for (int j = 0; j < Nn; ++j) {
                int o = (int)rois[j*5];
                r += (o < my) || (o == my && j < n);
            }
            g_rank[n] = r;
        }
    }
}

// ---------------- v partials: grid (8 d-tiles, 16 k-slices); V_box read once ----
__global__ void k_v(const float* __restrict__ V_box) {
    __shared__ __align__(16) float eps_s[Nn*128]; // 16 KB
    int dp = blockIdx.x, ks = blockIdx.y;
    int f0 = ks * 128;
    for (int i = threadIdx.x; i < Nn*128; i += 256) {
        int n = i >> 7, f = i & 127;
        eps_s[i] = g_eps[n*FDn + f0 + f];
    }
    __syncthreads();
    int dl = threadIdx.x & 63, ng = threadIdx.x >> 6;
    int d  = dp*64 + dl, n0 = ng*8;
    const ulonglong2* vb = (const ulonglong2*)(V_box + (size_t)d*FDn + f0);
    u64 acc[8] = {0,0,0,0,0,0,0,0};
    #pragma unroll 4
    for (int f = 0; f < 32; ++f) {
        ulonglong2 wv = vb[f];
        #pragma unroll
        for (int j = 0; j < 8; ++j) {
            ulonglong2 vv = *(const ulonglong2*)(eps_s + (n0+j)*128 + f*4);
            ffma2(acc[j], wv.x, vv.x);
            ffma2(acc[j], wv.y, vv.y);
        }
    }
    #pragma unroll
    for (int j = 0; j < 8; ++j)
        g_vp[(size_t)ks*(Nn*Dn) + (size_t)(n0+j)*Dn + d] = hsum2(acc[j]);
}

// ---------------- bvec[n,ko] = W_box[ko,:] . v[n,:] (reduces v partials) ----
__global__ void k_bvec(const float* __restrict__ W_box) {
    extern __shared__ __align__(16) float v_s[]; // 64 KB
    for (int i = threadIdx.x; i < Nn*Dn; i += 256) {
        float s = 0.f;
        #pragma unroll
        for (int p = 0; p < KSPLIT; ++p) s += g_vp[p*(Nn*Dn) + i];
        v_s[i] = s;
    }
    __syncthreads();
    int kol = threadIdx.x & 63;
    int ng  = threadIdx.x >> 6;
    int n0  = ng * 8;
    int ko  = blockIdx.x * 64 + kol;
    const ulonglong2* wb = (const ulonglong2*)(W_box + (size_t)ko * Dn);
    u64 acc[8] = {0,0,0,0,0,0,0,0};
    #pragma unroll 2
    for (int f = 0; f < Dn/4; ++f) {
        ulonglong2 wv = wb[f];
        #pragma unroll
        for (int j = 0; j < 8; ++j) {
            ulonglong2 vv = *(const ulonglong2*)(v_s + (n0+j)*Dn + f*4);
            ffma2(acc[j], wv.x, vv.x);
            ffma2(acc[j], wv.y, vv.y);
        }
    }
    #pragma unroll
    for (int j = 0; j < 8; ++j)
        g_bvec[(size_t)(n0+j)*KOn + ko] = hsum2(acc[j]);
}

// ---------------- eGA / eGB fused: blockIdx.y=0 -> GA (h), =1 -> GB (w) ----
__global__ void k_GAB() {
    extern __shared__ float M_s[]; // [o*(L+1) + l]
    int n = blockIdx.x;
    bool isA = (blockIdx.y == 0);
    int L  = isA ? Hn : Wn;
    int Lp = L + 1;
    const float* src = isA ? g_A : g_Bm;
    for (int i = threadIdx.x; i < L*On; i += 256) {
        int l = i >> 8, o = i & 255;
        M_s[o*Lp + l] = src[i];
    }
    __syncthreads();
    float* dst = isA ? (g_eGA + n*Kn*Hn) : (g_eGB + n*Kn*Wn);
    for (int idx = threadIdx.x; idx < Kn*L; idx += 256) {
        int k = idx / L, l = idx - k*L;
        const float4* bp = (const float4*)(g_bvec + ((size_t)n*Kn + k)*On);
        float acc = 0.f;
        #pragma unroll 4
        for (int o4 = 0; o4 < On/4; ++o4) {
            float4 bv = bp[o4];
            int ob = o4*4;
            acc += bv.x*M_s[ ob   *Lp + l] + bv.y*M_s[(ob+1)*Lp + l]
                 + bv.z*M_s[(ob+2)*Lp + l] + bv.w*M_s[(ob+3)*Lp + l];
        }
        dst[idx] = expf(acc);
    }
}

// ---------------- eapp[b,k,p] = exp( conv_b[k] + sum_c conv_w[k,c]*x[b,c,p] ) ----
__global__ void k_eapp(const float* __restrict__ x,
                       const float* __restrict__ conv_w,
                       const float* __restrict__ conv_b) {
    extern __shared__ float sm[];
    float* cw_s = sm;            // 52*256
    float* x_s  = sm + 52*256;   // 64 c x 64 p
    int b   = blockIdx.y;
    int px0 = blockIdx.x * 64;
    for (int i = threadIdx.x; i < 52*256; i += 128)
        cw_s[i] = (i < Kn*Cn) ? conv_w[i] : 0.0f;
    int lane = threadIdx.x & 31;
    int ks   = threadIdx.x >> 5;
    int k0   = ks * 13;
    float acc0[13], acc1[13];
    #pragma unroll
    for (int kk = 0; kk < 13; ++kk) { acc0[kk] = 0.f; acc1[kk] = 0.f; }

    for (int c0 = 0; c0 < Cn; c0 += 64) {
        __syncthreads();
        for (int i = threadIdx.x; i < 64*64; i += 128) {
            int c = i >> 6, p = i & 63;
            x_s[i] = x[((size_t)b*Cn + c0 + c)*HWn + px0 + p];
        }
        __syncthreads();
        #pragma unroll 4
        for (int c = 0; c < 64; ++c) {
            float xv0 = x_s[c*64 + lane*2];
            float xv1 = x_s[c*64 + lane*2 + 1];
            #pragma unroll
            for (int kk = 0; kk < 13; ++kk) {
                float wv = cw_s[(k0+kk)*256 + c0 + c];
                acc0[kk] += wv * xv0;
                acc1[kk] += wv * xv1;
            }
        }
    }
    int p0 = px0 + lane*2;
    #pragma unroll
    for (int kk = 0; kk < 13; ++kk) {
        int k = k0 + kk;
        if (k < Kn) {
            float bias = conv_b[k];
            g_eapp[((size_t)b*Kn + k)*HWn + p0    ] = expf(acc0[kk] + bias);
            g_eapp[((size_t)b*Kn + k)*HWn + p0 + 1] = expf(acc1[kk] + bias);
        }
    }
}

// ---------------- final: softmax over k, permuted write (77 MB store-bound) ----
__global__ void k_final(float* __restrict__ out) {
    __shared__ float eGA_s[Kn*Hn];
    __shared__ float eGB_s[Kn*Wn];
    int nb = blockIdx.y;
    int n = nb >> 2, b = nb & 3;
    for (int i = threadIdx.x; i < Kn*Hn; i += 256) eGA_s[i] = g_eGA[n*Kn*Hn + i];
    for (int i = threadIdx.x; i < Kn*Wn; i += 256) eGB_s[i] = g_eGB[n*Kn*Wn + i];
    __syncthreads();
    int p = blockIdx.x*256 + threadIdx.x;
    int h = p / 48;
    int w = p - h*48;
    const float* ea = g_eapp + (size_t)b*Kn*HWn + p;
    float s = 0.f;
    #pragma unroll
    for (int k = 0; k < Kn; ++k)
        s += eGA_s[k*Hn + h] * eGB_s[k*Wn + w] * ea[(size_t)k*HWn];
    float inv = 1.0f / s;
    int r = g_rank[n];
    float* op = out + ((size_t)(r*Bn + b)*Kn)*HWn + p;
    #pragma unroll
    for (int k = 0; k < Kn; ++k)
        op[(size_t)k*HWn] = eGA_s[k*Hn + h] * eGB_s[k*Wn + w] * ea[(size_t)k*HWn] * inv;
}

extern "C" void kernel_launch(void* const* d_in, const int* in_sizes, int n_in,
                              void* d_out, int out_size) {
    const float* x      = (const float*)d_in[0];
    const float* rois   = (const float*)d_in[1];
    const float* V_box  = (const float*)d_in[2];
    const float* W_box  = (const float*)d_in[3];
    const float* W_im   = (const float*)d_in[4];
    const float* conv_w = (const float*)d_in[5];
    const float* conv_b = (const float*)d_in[6];
    float* out = (float*)d_out;

    cudaFuncSetAttribute(k_bvec, cudaFuncAttributeMaxDynamicSharedMemorySize, 65536);
    cudaFuncSetAttribute(k_GAB,  cudaFuncAttributeMaxDynamicSharedMemorySize, 256*65*4);
    cudaFuncSetAttribute(k_eapp, cudaFuncAttributeMaxDynamicSharedMemorySize, 52*256*4 + 64*64*4);

    k_tab  <<<2, 256>>>();
    k_pre  <<<Nn + Hn + Wn + 1, 256>>>(rois, W_im);
    k_v    <<<dim3(8, KSPLIT), 256>>>(V_box);
    k_bvec <<<KOn/64, 256, 65536>>>(W_box);
    k_GAB  <<<dim3(Nn, 2), 256, 256*65*4>>>();
    k_eapp <<<dim3(HWn/64, Bn), 128, 52*256*4 + 64*64*4>>>(x, conv_w, conv_b);
    k_final<<<dim3(HWn/256, Nn*Bn), 256>>>(out);
}

// round 4
// speedup vs baseline: 2.4449x; 1.6535x over previous
#include <cuda_runtime.h>
#include <math.h>

#define Dn   512
#define FDn  2048
#define On   256
#define Kn   49
#define Bn   4
#define Cn   256
#define Hn   64
#define Wn   48
#define HWn  3072
#define Nn   32
#define KOn  (Kn*On)   // 12544
#define VSPLIT 16
#define BSPLIT 4

typedef unsigned long long u64;

__device__ float  g_eps [Nn*FDn];
__device__ float  g_vp  [VSPLIT*Nn*Dn];
__device__ float  g_v   [Nn*Dn];
__device__ float  g_bvp [BSPLIT*Nn*KOn];   // 6.4 MB partials
__device__ float  g_A   [Hn*On];
__device__ float  g_Bm  [Wn*On];
__device__ float  g_eGA [Nn*Kn*Hn];
__device__ float  g_eGB [Nn*Kn*Wn];
__device__ float  g_appp[2*Bn*Kn*HWn];     // conv partials (2 C-halves)
__device__ float  g_eapp[Bn*Kn*HWn];
__device__ int    g_rank[Nn];
__device__ double g_invden[512];

__device__ __forceinline__ void ffma2(u64 &acc, u64 a, u64 b) {
    asm volatile("fma.rn.f32x2 %0, %1, %2, %0;" : "+l"(acc) : "l"(a), "l"(b));
}
__device__ __forceinline__ float hsum2(u64 a) {
    float2 f = *reinterpret_cast<float2*>(&a);
    return f.x + f.y;
}

// ---------------- denominator table ----------------
__global__ void k_tab() {
    int dd = threadIdx.x + blockIdx.x * blockDim.x;
    if (dd < 512) {
        double e = (dd < 256) ? (2.0 * dd + 1.0) / 512.0
                              : (2.0 * (dd - 256)) / 512.0;
        g_invden[dd] = pow(1000.0, -e);
    }
}

__device__ __forceinline__ float embed_val(float z, int dd) {
    double a = (double)z * g_invden[dd];
    return (float)((dd < 256) ? sin(a) : cos(a));
}

// ---------------- fused: eps | A/B | rank ----------------
__global__ void k_pre(const float* __restrict__ rois,
                      const float* __restrict__ W_im) {
    int bid = blockIdx.x;
    if (bid < Nn) {
        int n = bid;
        float c0 = rois[n*5+1], c1 = rois[n*5+2], c2 = rois[n*5+3], c3 = rois[n*5+4];
        for (int i = threadIdx.x; i < FDn; i += blockDim.x) {
            int c  = i >> 9;
            int dd = i & 511;
            float z = (c >= 2) ? ((c == 3) ? c3 : c2) : ((c == 1) ? c1 : c0);
            g_eps[n*FDn + i] = embed_val(z, dd);
        }
    } else if (bid < Nn + Hn + Wn) {
        __shared__ __align__(16) float pe[Dn];
        int j = bid - Nn;
        bool isA = (j < Hn);
        float z = (float)(isA ? j : (j - Hn));
        for (int dd = threadIdx.x; dd < Dn; dd += blockDim.x)
            pe[dd] = embed_val(z, dd);
        __syncthreads();
        int o = threadIdx.x;
        const ulonglong2* w2 = (const ulonglong2*)(W_im + (size_t)o * (2*Dn) + (isA ? 0 : Dn));
        const ulonglong2* p2 = (const ulonglong2*)pe;
        u64 acc = 0;
        #pragma unroll 8
        for (int f = 0; f < Dn/4; ++f) {
            ulonglong2 wv = w2[f], pv = p2[f];
            ffma2(acc, wv.x, pv.x);
            ffma2(acc, wv.y, pv.y);
        }
        if (isA) g_A[j*On + o] = hsum2(acc);
        else     g_Bm[(j-Hn)*On + o] = hsum2(acc);
    } else {
        int n = threadIdx.x;
        if (n < Nn) {
            int my = (int)rois[n*5];
            int r = 0;
            for (int j = 0; j < Nn; ++j) {
                int o = (int)rois[j*5];
                r += (o < my) || (o == my && j < n);
            }
            g_rank[n] = r;
        }
    }
}

// ---------------- v partials: grid (8 d-tiles, 16 k-slices) ----------------
__global__ void k_v(const float* __restrict__ V_box) {
    __shared__ __align__(16) float eps_s[Nn*128]; // 16 KB
    int dp = blockIdx.x, ks = blockIdx.y;
    int f0 = ks * 128;
    for (int i = threadIdx.x; i < Nn*128; i += 256) {
        int n = i >> 7, f = i & 127;
        eps_s[i] = g_eps[n*FDn + f0 + f];
    }
    __syncthreads();
    int dl = threadIdx.x & 63, ng = threadIdx.x >> 6;
    int d  = dp*64 + dl, n0 = ng*8;
    const ulonglong2* vb = (const ulonglong2*)(V_box + (size_t)d*FDn + f0);
    u64 acc[8] = {0,0,0,0,0,0,0,0};
    #pragma unroll 8
    for (int f = 0; f < 32; ++f) {
        ulonglong2 wv = vb[f];
        #pragma unroll
        for (int j = 0; j < 8; ++j) {
            ulonglong2 vv = *(const ulonglong2*)(eps_s + (n0+j)*128 + f*4);
            ffma2(acc[j], wv.x, vv.x);
            ffma2(acc[j], wv.y, vv.y);
        }
    }
    #pragma unroll
    for (int j = 0; j < 8; ++j)
        g_vp[(size_t)ks*(Nn*Dn) + (size_t)(n0+j)*Dn + d] = hsum2(acc[j]);
}

// ---------------- reduce v partials ----------------
__global__ void k_vred() {
    int i = blockIdx.x*256 + threadIdx.x;   // 16384 outputs
    float s = 0.f;
    #pragma unroll
    for (int p = 0; p < VSPLIT; ++p) s += g_vp[p*(Nn*Dn) + i];
    g_v[i] = s;
}

// ---------------- bvec partials: grid (196 ko-tiles, 4 k-slices) ----------------
__global__ void k_bvec(const float* __restrict__ W_box) {
    __shared__ __align__(16) float v_s[Nn*128]; // 16 KB
    int ks = blockIdx.y;
    int f0 = ks * 128;
    for (int i = threadIdx.x; i < Nn*128; i += 256) {
        int n = i >> 7, fl = i & 127;
        v_s[i] = g_v[n*Dn + f0 + fl];
    }
    __syncthreads();
    int kol = threadIdx.x & 63;
    int ng  = threadIdx.x >> 6;
    int n0  = ng * 8;
    int ko  = blockIdx.x * 64 + kol;
    const ulonglong2* wb = (const ulonglong2*)(W_box + (size_t)ko * Dn + f0);
    u64 acc[8] = {0,0,0,0,0,0,0,0};
    #pragma unroll 8
    for (int f = 0; f < 32; ++f) {
        ulonglong2 wv = wb[f];
        #pragma unroll
        for (int j = 0; j < 8; ++j) {
            ulonglong2 vv = *(const ulonglong2*)(v_s + (n0+j)*128 + f*4);
            ffma2(acc[j], wv.x, vv.x);
            ffma2(acc[j], wv.y, vv.y);
        }
    }
    #pragma unroll
    for (int j = 0; j < 8; ++j)
        g_bvp[(size_t)ks*(Nn*KOn) + (size_t)(n0+j)*KOn + ko] = hsum2(acc[j]);
}

// ---------------- eGA/eGB: grid (n, side, 7 k-groups); reduces bvec partials ----
__global__ void k_GAB() {
    extern __shared__ __align__(16) float sm[];
    float* bv_s = sm;         // 7*256 floats
    float* M_s  = sm + 7*256; // 256*(L+1)
    int n  = blockIdx.x;
    bool isA = (blockIdx.y == 0);
    int kg = blockIdx.z;
    int k0 = kg * 7;
    int L  = isA ? Hn : Wn;
    int Lp = L + 1;
    const float* src = isA ? g_A : g_Bm;
    for (int i = threadIdx.x; i < 7*256; i += 256) {
        size_t base = (size_t)n*KOn + (size_t)k0*256 + i;
        float s = 0.f;
        #pragma unroll
        for (int p = 0; p < BSPLIT; ++p) s += g_bvp[(size_t)p*(Nn*KOn) + base];
        bv_s[i] = s;
    }
    for (int i = threadIdx.x; i < L*On; i += 256) {
        int l = i / On, o = i & 255;
        M_s[o*Lp + l] = src[i];
    }
    __syncthreads();
    float* dst = isA ? (g_eGA + n*Kn*Hn) : (g_eGB + n*Kn*Wn);
    if (isA) {
        for (int idx = threadIdx.x; idx < 7*Hn; idx += 256) {
            int kk = idx >> 6, l = idx & 63;
            const float4* bp = (const float4*)(bv_s + kk*256);
            float acc = 0.f;
            #pragma unroll 8
            for (int o4 = 0; o4 < 64; ++o4) {
                float4 bv = bp[o4];
                int ob = o4*4;
                acc += bv.x*M_s[ ob   *65 + l] + bv.y*M_s[(ob+1)*65 + l]
                     + bv.z*M_s[(ob+2)*65 + l] + bv.w*M_s[(ob+3)*65 + l];
            }
            dst[(k0+kk)*Hn + l] = expf(acc);
        }
    } else {
        for (int idx = threadIdx.x; idx < 7*Wn; idx += 256) {
            int kk = idx / 48, l = idx - kk*48;
            const float4* bp = (const float4*)(bv_s + kk*256);
            float acc = 0.f;
            #pragma unroll 8
            for (int o4 = 0; o4 < 64; ++o4) {
                float4 bv = bp[o4];
                int ob = o4*4;
                acc += bv.x*M_s[ ob   *49 + l] + bv.y*M_s[(ob+1)*49 + l]
                     + bv.z*M_s[(ob+2)*49 + l] + bv.w*M_s[(ob+3)*49 + l];
            }
            dst[(k0+kk)*Wn + l] = expf(acc);
        }
    }
}

// ---------------- conv partials: grid (48 px-tiles, B, 2 c-halves), 128 thr ----
// thread = (kg 0..7 -> 7 k's, lane 0..15 -> 4 px)
__global__ void k_app(const float* __restrict__ x,
                      const float* __restrict__ conv_w) {
    __shared__ __align__(16) float cw_s[56*128]; // 28 KB (rows >=49 zero)
    __shared__ __align__(16) float x_s[64*64];   // 16 KB
    int b   = blockIdx.y;
    int ch  = blockIdx.z;          // C half
    int px0 = blockIdx.x * 64;
    int cbase = ch * 128;
    for (int i = threadIdx.x; i < 56*128; i += 128) {
        int k = i >> 7, c = i & 127;
        cw_s[i] = (k < Kn) ? conv_w[k*Cn + cbase + c] : 0.0f;
    }
    int lane = threadIdx.x & 15;
    int kg   = threadIdx.x >> 4;
    int k0   = kg * 7;
    u64 acc[7][2];
    #pragma unroll
    for (int kk = 0; kk < 7; ++kk) { acc[kk][0] = 0; acc[kk][1] = 0; }

    for (int cb = 0; cb < 128; cb += 64) {
        __syncthreads();
        for (int i = threadIdx.x; i < 64*64; i += 128) {
            int c = i >> 6, p = i & 63;
            x_s[i] = x[((size_t)b*Cn + cbase + cb + c)*HWn + px0 + p];
        }
        __syncthreads();
        #pragma unroll 4
        for (int c = 0; c < 64; ++c) {
            ulonglong2 xv = *(const ulonglong2*)(x_s + c*64 + lane*4);
            #pragma unroll
            for (int kk = 0; kk < 7; ++kk) {
                float w = cw_s[(k0+kk)*128 + cb + c];
                u64 w2; asm("mov.b64 %0, {%1, %1};" : "=l"(w2) : "f"(w));
                ffma2(acc[kk][0], w2, xv.x);
                ffma2(acc[kk][1], w2, xv.y);
            }
        }
    }
    int p0 = px0 + lane*4;
    #pragma unroll
    for (int kk = 0; kk < 7; ++kk) {
        int k = k0 + kk;
        if (k < Kn) {
            float4 v;
            v.x = ((float2*)&acc[kk][0])->x; v.y = ((float2*)&acc[kk][0])->y;
            v.z = ((float2*)&acc[kk][1])->x; v.w = ((float2*)&acc[kk][1])->y;
            *(float4*)(g_appp + ((size_t)ch*Bn*Kn + (size_t)b*Kn + k)*HWn + p0) = v;
        }
    }
}

// ---------------- combine conv halves + bias + exp ----------------
__global__ void k_ecomb(const float* __restrict__ conv_b) {
    int i = blockIdx.x*256 + threadIdx.x;   // Bn*Kn*HWn
    int kb = i / HWn;       // 0..195
    int k  = kb % Kn;
    float s = g_appp[i] + g_appp[(size_t)Bn*Kn*HWn + i] + conv_b[k];
    g_eapp[i] = expf(s);
}

// ---------------- final: softmax over k, permuted write ----------------
__global__ void k_final(float* __restrict__ out) {
    __shared__ float eGA_s[Kn*Hn];
    __shared__ float eGB_s[Kn*Wn];
    int nb = blockIdx.y;
    int n = nb >> 2, b = nb & 3;
    for (int i = threadIdx.x; i < Kn*Hn; i += 256) eGA_s[i] = g_eGA[n*Kn*Hn + i];
    for (int i = threadIdx.x; i < Kn*Wn; i += 256) eGB_s[i] = g_eGB[n*Kn*Wn + i];
    __syncthreads();
    int p = blockIdx.x*256 + threadIdx.x;
    int h = p / 48;
    int w = p - h*48;
    const float* ea = g_eapp + (size_t)b*Kn*HWn + p;
    float s = 0.f;
    #pragma unroll
    for (int k = 0; k < Kn; ++k)
        s += eGA_s[k*Hn + h] * eGB_s[k*Wn + w] * ea[(size_t)k*HWn];
    float inv = 1.0f / s;
    int r = g_rank[n];
    float* op = out + ((size_t)(r*Bn + b)*Kn)*HWn + p;
    #pragma unroll
    for (int k = 0; k < Kn; ++k)
        op[(size_t)k*HWn] = eGA_s[k*Hn + h] * eGB_s[k*Wn + w] * ea[(size_t)k*HWn] * inv;
}

extern "C" void kernel_launch(void* const* d_in, const int* in_sizes, int n_in,
                              void* d_out, int out_size) {
    const float* x      = (const float*)d_in[0];
    const float* rois   = (const float*)d_in[1];
    const float* V_box  = (const float*)d_in[2];
    const float* W_box  = (const float*)d_in[3];
    const float* W_im   = (const float*)d_in[4];
    const float* conv_w = (const float*)d_in[5];
    const float* conv_b = (const float*)d_in[6];
    float* out = (float*)d_out;

    cudaFuncSetAttribute(k_GAB, cudaFuncAttributeMaxDynamicSharedMemorySize,
                         (7*256 + 256*65) * 4);

    k_tab  <<<2, 256>>>();
    k_pre  <<<Nn + Hn + Wn + 1, 256>>>(rois, W_im);
    k_v    <<<dim3(8, VSPLIT), 256>>>(V_box);
    k_vred <<<Nn*Dn/256, 256>>>();
    k_bvec <<<dim3(KOn/64, BSPLIT), 256>>>(W_box);
    k_GAB  <<<dim3(Nn, 2, 7), 256, (7*256 + 256*65)*4>>>();
    k_app  <<<dim3(HWn/64, Bn, 2), 128>>>(x, conv_w);
    k_ecomb<<<Bn*Kn*HWn/256, 256>>>(conv_b);
    k_final<<<dim3(HWn/256, Nn*Bn), 256>>>(out);
}